// round 3
// baseline (speedup 1.0000x reference)
#include <cuda_runtime.h>
#include <cuda_bf16.h>

#define D 64
#define N_MAX 131072
#define E_MAX 2097152

// -------- device scratch (no allocations allowed) --------
__device__ float g_H[N_MAX * D];     // post-GEMM features
__device__ float g_A[N_MAX * D];     // post-aggregation activations
__device__ int   g_cnt[N_MAX];       // in-degree (without self loop)
__device__ float g_dinv[N_MAX];      // deg^{-1/2} (with self loop)
__device__ int   g_rowtmp[N_MAX];
__device__ int   g_rowptr[N_MAX + 1];
__device__ int   g_cursor[N_MAX];
__device__ int   g_part[256];
__device__ int   g_col[E_MAX];
__device__ float g_norm[E_MAX];
__device__ int   g_elw;              // edge-index element width in int32 units (1=int32, 2=int64)

// -------- dtype probe --------
// int64 buffer with values < 2^31 has zero in every odd int32 slot.
// int32 buffer has real edge values there (nonzero w.h.p.).
__global__ void k_probe(const int* __restrict__ p) {
    if (threadIdx.x == 0) {
        int nz = 0;
#pragma unroll
        for (int k = 0; k < 64; k++) nz |= p[2 * k + 1];
        g_elw = (nz == 0) ? 2 : 1;
    }
}

// -------- setup kernels --------
__global__ void k_init(int n) {
    int i = blockIdx.x * blockDim.x + threadIdx.x;
    if (i < n) { g_cnt[i] = 0; g_cursor[i] = 0; }
}

__global__ void k_count(const int* __restrict__ p, int e, int n) {
    int t = blockIdx.x * blockDim.x + threadIdx.x;
    if (t < e) {
        int elw = g_elw;
        int dst = p[elw * (e + t)];
        if ((unsigned)dst < (unsigned)n) atomicAdd(&g_cnt[dst], 1);
    }
}

__global__ void k_dinv(int n) {
    int i = blockIdx.x * blockDim.x + threadIdx.x;
    if (i < n) g_dinv[i] = rsqrtf((float)(g_cnt[i] + 1));
}

__global__ void k_scanA(int n) {
    __shared__ int sh[1024];
    int i = blockIdx.x * 1024 + threadIdx.x;
    int v = (i < n) ? g_cnt[i] : 0;
    sh[threadIdx.x] = v;
    __syncthreads();
#pragma unroll
    for (int off = 1; off < 1024; off <<= 1) {
        int t = (threadIdx.x >= off) ? sh[threadIdx.x - off] : 0;
        __syncthreads();
        sh[threadIdx.x] += t;
        __syncthreads();
    }
    if (i < n) g_rowtmp[i] = sh[threadIdx.x] - v;  // exclusive
    if (threadIdx.x == 1023) g_part[blockIdx.x] = sh[1023];
}

__global__ void k_scanB(int nb) {
    if (threadIdx.x == 0) {
        int run = 0;
        for (int b = 0; b < nb; b++) { int t = g_part[b]; g_part[b] = run; run += t; }
    }
}

__global__ void k_scanC(int n, int e) {
    int i = blockIdx.x * blockDim.x + threadIdx.x;
    if (i < n) g_rowptr[i] = g_rowtmp[i] + g_part[i >> 10];
    if (i == 0) g_rowptr[n] = e;
}

__global__ void k_fill(const int* __restrict__ p, int e, int n) {
    int t = blockIdx.x * blockDim.x + threadIdx.x;
    if (t < e) {
        int elw = g_elw;
        int src = p[elw * t];
        int dst = p[elw * (e + t)];
        if ((unsigned)src < (unsigned)n && (unsigned)dst < (unsigned)n) {
            int pos = g_rowptr[dst] + atomicAdd(&g_cursor[dst], 1);
            g_col[pos] = src;
            g_norm[pos] = g_dinv[src] * g_dinv[dst];
        }
    }
}

// -------- GEMM: g_H[n,64] = A[n,64] @ W[64,64] --------
// SRC: 0 = external pointer (x), 1 = g_A.
// 256 threads = 8 warps; each warp computes 4 rows; W staged in smem.
template <int SRC>
__global__ void k_gemm(const float* __restrict__ Aext, const float* __restrict__ W,
                       int n) {
    __shared__ float Ws[64 * 64];
    int tid = threadIdx.x;
    const float4* W4 = (const float4*)W;
    float4* Ws4 = (float4*)Ws;
#pragma unroll
    for (int i = 0; i < 4; i++) Ws4[tid + i * 256] = W4[tid + i * 256];
    __syncthreads();

    const float* A = (SRC == 0) ? Aext : (const float*)g_A;

    int warp = tid >> 5, lane = tid & 31;
    int row0 = (blockIdx.x * 8 + warp) * 4;

    float a[4][2];
    float2 acc[4];
#pragma unroll
    for (int r = 0; r < 4; r++) {
        int row = row0 + r;
        if (row < n) {
            a[r][0] = A[row * 64 + lane];
            a[r][1] = A[row * 64 + lane + 32];
        } else { a[r][0] = 0.f; a[r][1] = 0.f; }
        acc[r] = make_float2(0.f, 0.f);
    }

    const float2* Ws2 = (const float2*)Ws;
#pragma unroll
    for (int k = 0; k < 64; k++) {
        float2 w = Ws2[k * 32 + lane];
#pragma unroll
        for (int r = 0; r < 4; r++) {
            float ak = __shfl_sync(0xffffffffu, a[r][k >> 5], k & 31);
            acc[r].x += ak * w.x;
            acc[r].y += ak * w.y;
        }
    }
#pragma unroll
    for (int r = 0; r < 4; r++) {
        int row = row0 + r;
        if (row < n) ((float2*)g_H)[row * 32 + lane] = acc[r];
    }
}

// -------- Aggregation --------
// out[i] = relu( sum_{e: dst=i} norm_e * H[src_e] + dinv_i^2 * H[i] + b )
// DSTOUT: 0 = write g_A, 1 = write external out pointer. Input always g_H.
// one warp per node, lane handles 2 consecutive floats (float2)
template <int DSTOUT>
__global__ void k_agg(const float* __restrict__ bias, float* __restrict__ outext,
                      int n) {
    int gw = (blockIdx.x * blockDim.x + threadIdx.x) >> 5;
    int lane = threadIdx.x & 31;
    if (gw >= n) return;
    int i = gw;

    const float2* H2 = (const float2*)g_H;
    float di = g_dinv[i];
    float sn = di * di;
    float2 h = H2[i * 32 + lane];
    float2 acc = make_float2(h.x * sn, h.y * sn);

    int s = g_rowptr[i], e = g_rowptr[i + 1];
    for (int base = s; base < e; base += 32) {
        int m = min(32, e - base);
        int c = 0; float nv = 0.f;
        if (lane < m) { c = g_col[base + lane]; nv = g_norm[base + lane]; }
#pragma unroll 4
        for (int j = 0; j < m; j++) {
            int   cj = __shfl_sync(0xffffffffu, c, j);
            float nj = __shfl_sync(0xffffffffu, nv, j);
            float2 hh = H2[cj * 32 + lane];
            acc.x += hh.x * nj;
            acc.y += hh.y * nj;
        }
    }
    float2 bb = ((const float2*)bias)[lane];
    acc.x = fmaxf(acc.x + bb.x, 0.f);
    acc.y = fmaxf(acc.y + bb.y, 0.f);
    float2* outp = (DSTOUT == 0) ? (float2*)g_A : (float2*)outext;
    outp[i * 32 + lane] = acc;
}

// -------- launch --------
extern "C" void kernel_launch(void* const* d_in, const int* in_sizes, int n_in,
                              void* d_out, int out_size) {
    const float* x  = (const float*)d_in[0];
    const int*   ei = (const int*)d_in[1];   // int32 or int64; probed on device
    const float* W0 = (const float*)d_in[2];
    const float* b0 = (const float*)d_in[3];
    const float* W1 = (const float*)d_in[4];
    const float* b1 = (const float*)d_in[5];
    const float* W2 = (const float*)d_in[6];
    const float* b2 = (const float*)d_in[7];
    float* out = (float*)d_out;

    int n = in_sizes[0] / D;
    int e = in_sizes[1] / 2;

    int nb = (n + 1023) / 1024;

    k_probe<<<1, 32>>>(ei);
    k_init <<<(n + 255) / 256, 256>>>(n);
    k_count<<<(e + 255) / 256, 256>>>(ei, e, n);
    k_dinv <<<(n + 255) / 256, 256>>>(n);
    k_scanA<<<nb, 1024>>>(n);
    k_scanB<<<1, 32>>>(nb);
    k_scanC<<<(n + 255) / 256, 256>>>(n, e);
    k_fill <<<(e + 255) / 256, 256>>>(ei, e, n);

    int gemm_blocks = (n + 31) / 32;
    int agg_blocks  = (n + 7) / 8;   // 8 warps/block, 1 warp/node

    // layer 0
    k_gemm<0><<<gemm_blocks, 256>>>(x,  W0, n);
    k_agg<0> <<<agg_blocks, 256>>>(b0, nullptr, n);
    // layer 1
    k_gemm<1><<<gemm_blocks, 256>>>(nullptr, W1, n);
    k_agg<0> <<<agg_blocks, 256>>>(b1, nullptr, n);
    // layer 2
    k_gemm<1><<<gemm_blocks, 256>>>(nullptr, W2, n);
    k_agg<1> <<<agg_blocks, 256>>>(b2, out, n);
}

// round 4
// speedup vs baseline: 1.0436x; 1.0436x over previous
#include <cuda_runtime.h>
#include <cuda_bf16.h>

#define D 64
#define N_MAX 131072
#define E_MAX 2097152

// -------- device scratch --------
__device__ float g_H[N_MAX * D];
__device__ float g_A[N_MAX * D];
__device__ int   g_cnt[N_MAX];
__device__ float g_dinv[N_MAX];
__device__ int   g_rowtmp[N_MAX];
__device__ int   g_rowptr[N_MAX + 1];
__device__ int   g_cursor[N_MAX];
__device__ int   g_part[256];
__device__ int   g_col[E_MAX];
__device__ float g_norm[E_MAX];
__device__ int   g_elw;   // 1 = int32 edge index, 2 = int64

// -------- init + dtype probe (fused) --------
__global__ void k_init(const int* __restrict__ p, int n) {
    int i = blockIdx.x * blockDim.x + threadIdx.x;
    if (i < n) { g_cnt[i] = 0; g_cursor[i] = 0; }
    if (blockIdx.x == 0 && threadIdx.x == 0) {
        int nz = 0;
#pragma unroll
        for (int k = 0; k < 64; k++) nz |= p[2 * k + 1];
        g_elw = (nz == 0) ? 2 : 1;
    }
}

// -------- degree count: 4 edges per thread, vectorized --------
__global__ void k_count(const int* __restrict__ p, int e, int n) {
    int base = (blockIdx.x * blockDim.x + threadIdx.x) * 4;
    if (base >= e) return;
    int elw = g_elw;
    int d[4];
    bool full = (base + 3 < e) && ((e & 3) == 0);
    if (elw == 1) {
        if (full) {
            int4 v = *(const int4*)(p + e + base);
            d[0] = v.x; d[1] = v.y; d[2] = v.z; d[3] = v.w;
        } else {
            for (int i = 0; i < 4; i++) d[i] = (base + i < e) ? p[e + base + i] : -1;
        }
    } else {
        const long long* q = (const long long*)p;
        if (full) {
            longlong2 v0 = *(const longlong2*)(q + e + base);
            longlong2 v1 = *(const longlong2*)(q + e + base + 2);
            d[0] = (int)v0.x; d[1] = (int)v0.y; d[2] = (int)v1.x; d[3] = (int)v1.y;
        } else {
            for (int i = 0; i < 4; i++) d[i] = (base + i < e) ? (int)q[e + base + i] : -1;
        }
    }
#pragma unroll
    for (int i = 0; i < 4; i++)
        if ((unsigned)d[i] < (unsigned)n) atomicAdd(&g_cnt[d[i]], 1);
}

// -------- block scan (+ fused dinv) --------
__global__ void k_scanA(int n) {
    __shared__ int sh[1024];
    int i = blockIdx.x * 1024 + threadIdx.x;
    int v = (i < n) ? g_cnt[i] : 0;
    if (i < n) g_dinv[i] = rsqrtf((float)(v + 1));
    sh[threadIdx.x] = v;
    __syncthreads();
#pragma unroll
    for (int off = 1; off < 1024; off <<= 1) {
        int t = (threadIdx.x >= off) ? sh[threadIdx.x - off] : 0;
        __syncthreads();
        sh[threadIdx.x] += t;
        __syncthreads();
    }
    if (i < n) g_rowtmp[i] = sh[threadIdx.x] - v;
    if (threadIdx.x == 1023) g_part[blockIdx.x] = sh[1023];
}

__global__ void k_scanB(int nb) {
    if (threadIdx.x == 0) {
        int run = 0;
        for (int b = 0; b < nb; b++) { int t = g_part[b]; g_part[b] = run; run += t; }
    }
}

__global__ void k_scanC(int n, int e) {
    int i = blockIdx.x * blockDim.x + threadIdx.x;
    if (i < n) g_rowptr[i] = g_rowtmp[i] + g_part[i >> 10];
    if (i == 0) g_rowptr[n] = e;
}

// -------- CSR fill: 4 edges per thread --------
__global__ void k_fill(const int* __restrict__ p, int e, int n) {
    int base = (blockIdx.x * blockDim.x + threadIdx.x) * 4;
    if (base >= e) return;
    int elw = g_elw;
    int s[4], d[4];
    bool full = (base + 3 < e) && ((e & 3) == 0);
    if (elw == 1) {
        if (full) {
            int4 vs = *(const int4*)(p + base);
            int4 vd = *(const int4*)(p + e + base);
            s[0] = vs.x; s[1] = vs.y; s[2] = vs.z; s[3] = vs.w;
            d[0] = vd.x; d[1] = vd.y; d[2] = vd.z; d[3] = vd.w;
        } else {
            for (int i = 0; i < 4; i++) {
                s[i] = (base + i < e) ? p[base + i] : -1;
                d[i] = (base + i < e) ? p[e + base + i] : -1;
            }
        }
    } else {
        const long long* q = (const long long*)p;
        if (full) {
            longlong2 s0 = *(const longlong2*)(q + base);
            longlong2 s1 = *(const longlong2*)(q + base + 2);
            longlong2 d0 = *(const longlong2*)(q + e + base);
            longlong2 d1 = *(const longlong2*)(q + e + base + 2);
            s[0] = (int)s0.x; s[1] = (int)s0.y; s[2] = (int)s1.x; s[3] = (int)s1.y;
            d[0] = (int)d0.x; d[1] = (int)d0.y; d[2] = (int)d1.x; d[3] = (int)d1.y;
        } else {
            for (int i = 0; i < 4; i++) {
                s[i] = (base + i < e) ? (int)q[base + i] : -1;
                d[i] = (base + i < e) ? (int)q[e + base + i] : -1;
            }
        }
    }
#pragma unroll
    for (int i = 0; i < 4; i++) {
        if ((unsigned)s[i] < (unsigned)n && (unsigned)d[i] < (unsigned)n) {
            int pos = g_rowptr[d[i]] + atomicAdd(&g_cursor[d[i]], 1);
            g_col[pos] = s[i];
            g_norm[pos] = g_dinv[s[i]] * g_dinv[d[i]];
        }
    }
}

// -------- GEMM: g_H[n,64] = A[n,64] @ W[64,64] --------
// 128 threads/block, 64 rows x 64 cols per block, 4x8 micro-tile per thread.
template <int SRC>
__global__ void __launch_bounds__(128) k_gemm(const float* __restrict__ Aext,
                                              const float* __restrict__ W, int n) {
    __shared__ float As[64][65];   // padded: conflict-free column reads
    __shared__ float Ws[64][64];

    const float* A = (SRC == 0) ? Aext : (const float*)g_A;
    int tid = threadIdx.x;
    int rowbase = blockIdx.x * 64;

    // stage A tile (64x64) and W (64x64); 8 float4 per thread each
#pragma unroll
    for (int i = 0; i < 8; i++) {
        int idx = tid + i * 128;        // 0..1023
        int r = idx >> 4;               // 0..63
        int f4 = idx & 15;              // 0..15
        float4 va = (rowbase + r < n)
            ? *(const float4*)(A + (size_t)(rowbase + r) * 64 + f4 * 4)
            : make_float4(0.f, 0.f, 0.f, 0.f);
        As[r][f4 * 4 + 0] = va.x; As[r][f4 * 4 + 1] = va.y;
        As[r][f4 * 4 + 2] = va.z; As[r][f4 * 4 + 3] = va.w;
        *(float4*)(&Ws[r][f4 * 4]) = *(const float4*)(W + r * 64 + f4 * 4);
    }
    __syncthreads();

    int tx = tid & 7;    // col group: cols tx*8..+7
    int ty = tid >> 3;   // row group: rows ty*4..+3

    float acc[4][8];
#pragma unroll
    for (int r = 0; r < 4; r++)
#pragma unroll
        for (int c = 0; c < 8; c++) acc[r][c] = 0.f;

#pragma unroll 4
    for (int k = 0; k < 64; k++) {
        float a0 = As[ty * 4 + 0][k];
        float a1 = As[ty * 4 + 1][k];
        float a2 = As[ty * 4 + 2][k];
        float a3 = As[ty * 4 + 3][k];
        float4 w0 = *(const float4*)(&Ws[k][tx * 8]);
        float4 w1 = *(const float4*)(&Ws[k][tx * 8 + 4]);
        float wv[8] = {w0.x, w0.y, w0.z, w0.w, w1.x, w1.y, w1.z, w1.w};
#pragma unroll
        for (int c = 0; c < 8; c++) {
            acc[0][c] += a0 * wv[c];
            acc[1][c] += a1 * wv[c];
            acc[2][c] += a2 * wv[c];
            acc[3][c] += a3 * wv[c];
        }
    }

#pragma unroll
    for (int r = 0; r < 4; r++) {
        int row = rowbase + ty * 4 + r;
        if (row < n) {
            float4 o0 = make_float4(acc[r][0], acc[r][1], acc[r][2], acc[r][3]);
            float4 o1 = make_float4(acc[r][4], acc[r][5], acc[r][6], acc[r][7]);
            *(float4*)(g_H + (size_t)row * 64 + tx * 8)     = o0;
            *(float4*)(g_H + (size_t)row * 64 + tx * 8 + 4) = o1;
        }
    }
}

// -------- Aggregation (warp per node) --------
template <int DSTOUT>
__global__ void k_agg(const float* __restrict__ bias, float* __restrict__ outext,
                      int n) {
    int gw = (blockIdx.x * blockDim.x + threadIdx.x) >> 5;
    int lane = threadIdx.x & 31;
    if (gw >= n) return;
    int i = gw;

    const float2* H2 = (const float2*)g_H;
    float di = g_dinv[i];
    float sn = di * di;
    float2 h = H2[i * 32 + lane];
    float2 acc = make_float2(h.x * sn, h.y * sn);

    int s = g_rowptr[i], e = g_rowptr[i + 1];
    for (int base = s; base < e; base += 32) {
        int m = min(32, e - base);
        int c = 0; float nv = 0.f;
        if (lane < m) { c = g_col[base + lane]; nv = g_norm[base + lane]; }
#pragma unroll 4
        for (int j = 0; j < m; j++) {
            int   cj = __shfl_sync(0xffffffffu, c, j);
            float nj = __shfl_sync(0xffffffffu, nv, j);
            float2 hh = __ldg(&H2[cj * 32 + lane]);
            acc.x += hh.x * nj;
            acc.y += hh.y * nj;
        }
    }
    float2 bb = ((const float2*)bias)[lane];
    acc.x = fmaxf(acc.x + bb.x, 0.f);
    acc.y = fmaxf(acc.y + bb.y, 0.f);
    float2* outp = (DSTOUT == 0) ? (float2*)g_A : (float2*)outext;
    outp[i * 32 + lane] = acc;
}

// -------- launch --------
extern "C" void kernel_launch(void* const* d_in, const int* in_sizes, int n_in,
                              void* d_out, int out_size) {
    const float* x  = (const float*)d_in[0];
    const int*   ei = (const int*)d_in[1];
    const float* W0 = (const float*)d_in[2];
    const float* b0 = (const float*)d_in[3];
    const float* W1 = (const float*)d_in[4];
    const float* b1 = (const float*)d_in[5];
    const float* W2 = (const float*)d_in[6];
    const float* b2 = (const float*)d_in[7];
    float* out = (float*)d_out;

    int n = in_sizes[0] / D;
    int e = in_sizes[1] / 2;
    int nb = (n + 1023) / 1024;
    int e4 = (e + 3) / 4;

    k_init <<<(n + 255) / 256, 256>>>(ei, n);
    k_count<<<(e4 + 255) / 256, 256>>>(ei, e, n);
    k_scanA<<<nb, 1024>>>(n);
    k_scanB<<<1, 32>>>(nb);
    k_scanC<<<(n + 255) / 256, 256>>>(n, e);
    k_fill <<<(e4 + 255) / 256, 256>>>(ei, e, n);

    int gemm_blocks = (n + 63) / 64;
    int agg_blocks  = (n + 7) / 8;

    k_gemm<0><<<gemm_blocks, 128>>>(x, W0, n);
    k_agg<0> <<<agg_blocks, 256>>>(b0, nullptr, n);
    k_gemm<1><<<gemm_blocks, 128>>>(nullptr, W1, n);
    k_agg<0> <<<agg_blocks, 256>>>(b1, nullptr, n);
    k_gemm<1><<<gemm_blocks, 128>>>(nullptr, W2, n);
    k_agg<1> <<<agg_blocks, 256>>>(b2, out, n);
}